// round 14
// baseline (speedup 1.0000x reference)
#include <cuda_runtime.h>
#include <cuda_bf16.h>
#include <cuda_fp16.h>
#include <mma.h>
#include <math.h>
#include <cstdint>

using namespace nvcuda;

#define B_ 8
#define S_ 1024
#define D_ 256
#define H_ 8
#define DH_ 32
#define BH_ (B_*H_)
#define ROWS 32
#define SS_STRIDE 1028
#define THREADS 1024
#define GT 256
#define KCH 32
#define GLDA 40
#define LDC 132
#define GBUF_BYTES (4 * 128 * GLDA * 2)    // 40960 per buffer
#define GS_TOTAL (2 * GBUF_BYTES)          // 81920 (> C tile 67584, aliased)

// Scratch (device globals: no allocation allowed)
__device__ __half g_Qh[BH_*S_*DH_], g_Ql[BH_*S_*DH_];
__device__ __half g_Kh[BH_*S_*DH_], g_Kl[BH_*S_*DH_];
__device__ __half g_Vh[BH_*S_*DH_], g_Vl[BH_*S_*DH_];
__device__ float  g_ctx[B_*S_*D_];

__device__ __forceinline__ void cvt_store_bf(
    __nv_bfloat16* hi, __nv_bfloat16* lo, int off, float4 x)
{
    __nv_bfloat16 hx = __float2bfloat16_rn(x.x);
    __nv_bfloat16 hy = __float2bfloat16_rn(x.y);
    __nv_bfloat16 hz = __float2bfloat16_rn(x.z);
    __nv_bfloat16 hw = __float2bfloat16_rn(x.w);
    *(__nv_bfloat162*)&hi[off]     = __nv_bfloat162(hx, hy);
    *(__nv_bfloat162*)&hi[off + 2] = __nv_bfloat162(hz, hw);
    *(__nv_bfloat162*)&lo[off] = __nv_bfloat162(
        __float2bfloat16_rn(x.x - __bfloat162float(hx)),
        __float2bfloat16_rn(x.y - __bfloat162float(hy)));
    *(__nv_bfloat162*)&lo[off + 2] = __nv_bfloat162(
        __float2bfloat16_rn(x.z - __bfloat162float(hz)),
        __float2bfloat16_rn(x.w - __bfloat162float(hw)));
}

// ---------------------------------------------------------------------------
// Tensor-core GEMM (wmma bf16 split 3-term, double-buffered): C = A@W^T + bias
// (unchanged from R13 — verified good)
// ---------------------------------------------------------------------------
__device__ __forceinline__ void gemm_tc_body(
    const float* __restrict__ A, const float* __restrict__ W,
    const float* __restrict__ bias, float* __restrict__ Cf,
    __half* __restrict__ Ch, __half* __restrict__ Cl, int mode, float outScale)
{
    extern __shared__ char gsm[];
    float* sC = (float*)gsm;
    int tid = threadIdx.x;
    int warp = tid >> 5;
    int m0 = blockIdx.y * 128, n0 = blockIdx.x * 128;
    int mw = (warp >> 2) * 64;
    int nw = (warp & 3) * 32;

    wmma::fragment<wmma::accumulator, 16, 16, 16, float> acc[4][2];
    #pragma unroll
    for (int i = 0; i < 4; i++)
        #pragma unroll
        for (int j = 0; j < 2; j++)
            wmma::fill_fragment(acc[i][j], 0.0f);

    float4 pa[4], pb[4];
    #pragma unroll
    for (int it = 0; it < 4; it++) {
        int idx = tid + it * GT;
        int r = idx >> 3, c4 = (idx & 7) << 2;
        pa[it] = *(const float4*)&A[(size_t)(m0 + r) * D_ + c4];
        pb[it] = *(const float4*)&W[(size_t)(n0 + r) * D_ + c4];
    }

    for (int kc = 0; kc < D_; kc += KCH) {
        char* bufb = gsm + (((kc >> 5) & 1) ? GBUF_BYTES : 0);
        __nv_bfloat16* bAhi = (__nv_bfloat16*)bufb;
        __nv_bfloat16* bAlo = bAhi + 128 * GLDA;
        __nv_bfloat16* bBhi = bAlo + 128 * GLDA;
        __nv_bfloat16* bBlo = bBhi + 128 * GLDA;

        #pragma unroll
        for (int it = 0; it < 4; it++) {
            int idx = tid + it * GT;
            int r = idx >> 3, c4 = (idx & 7) << 2;
            cvt_store_bf(bAhi, bAlo, r * GLDA + c4, pa[it]);
            cvt_store_bf(bBhi, bBlo, r * GLDA + c4, pb[it]);
        }
        __syncthreads();

        if (kc + KCH < D_) {
            #pragma unroll
            for (int it = 0; it < 4; it++) {
                int idx = tid + it * GT;
                int r = idx >> 3, c4 = (idx & 7) << 2;
                pa[it] = *(const float4*)&A[(size_t)(m0 + r) * D_ + kc + KCH + c4];
                pb[it] = *(const float4*)&W[(size_t)(n0 + r) * D_ + kc + KCH + c4];
            }
        }

        #pragma unroll
        for (int kk = 0; kk < KCH; kk += 16) {
            wmma::fragment<wmma::matrix_a, 16, 16, 16, __nv_bfloat16, wmma::row_major> ah[4], al[4];
            wmma::fragment<wmma::matrix_b, 16, 16, 16, __nv_bfloat16, wmma::col_major> bh[2], bl[2];
            #pragma unroll
            for (int i = 0; i < 4; i++) {
                wmma::load_matrix_sync(ah[i], &bAhi[(mw + i*16) * GLDA + kk], GLDA);
                wmma::load_matrix_sync(al[i], &bAlo[(mw + i*16) * GLDA + kk], GLDA);
            }
            #pragma unroll
            for (int j = 0; j < 2; j++) {
                wmma::load_matrix_sync(bh[j], &bBhi[(nw + j*16) * GLDA + kk], GLDA);
                wmma::load_matrix_sync(bl[j], &bBlo[(nw + j*16) * GLDA + kk], GLDA);
            }
            #pragma unroll
            for (int i = 0; i < 4; i++)
                #pragma unroll
                for (int j = 0; j < 2; j++) {
                    wmma::mma_sync(acc[i][j], ah[i], bh[j], acc[i][j]);
                    wmma::mma_sync(acc[i][j], ah[i], bl[j], acc[i][j]);
                    wmma::mma_sync(acc[i][j], al[i], bh[j], acc[i][j]);
                }
        }
        __syncthreads();
    }

    #pragma unroll
    for (int i = 0; i < 4; i++)
        #pragma unroll
        for (int j = 0; j < 2; j++)
            wmma::store_matrix_sync(&sC[(mw + i*16) * LDC + nw + j*16],
                                    acc[i][j], LDC, wmma::mem_row_major);
    __syncthreads();

    #pragma unroll
    for (int it = 0; it < 16; it++) {
        int idx = tid + it * GT;
        int r = idx >> 5, c4 = (idx & 31) << 2;
        float4 v = *(const float4*)&sC[r * LDC + c4];
        int n = n0 + c4;
        v.x += bias[n]; v.y += bias[n+1]; v.z += bias[n+2]; v.w += bias[n+3];
        int m = m0 + r, bbat = m >> 10, ss = m & 1023;
        if (mode == 1) {
            v.x *= outScale; v.y *= outScale; v.z *= outScale; v.w *= outScale;
            int h = n >> 5, dh = n & 31;
            size_t base = (((size_t)(bbat * H_ + h)) * S_ + ss) * DH_ + dh;
            __half hx = __float2half_rn(v.x), hy = __float2half_rn(v.y);
            __half hz = __float2half_rn(v.z), hw = __float2half_rn(v.w);
            *(__half2*)&Ch[base]     = __halves2half2(hx, hy);
            *(__half2*)&Ch[base + 2] = __halves2half2(hz, hw);
            *(__half2*)&Cl[base] = __halves2half2(
                __float2half_rn(v.x - __half2float(hx)),
                __float2half_rn(v.y - __half2float(hy)));
            *(__half2*)&Cl[base + 2] = __halves2half2(
                __float2half_rn(v.z - __half2float(hz)),
                __float2half_rn(v.w - __half2float(hw)));
        } else {
            *(float4*)&Cf[(size_t)m * D_ + n] = v;
        }
    }
}

__global__ __launch_bounds__(GT) void proj3_kernel(
    const float* __restrict__ q, const float* __restrict__ k, const float* __restrict__ v,
    const float* __restrict__ Wq, const float* __restrict__ bq,
    const float* __restrict__ Wv, const float* __restrict__ bv,
    __half* Qh, __half* Ql, __half* Kh, __half* Kl, __half* Vh, __half* Vl)
{
    int z = blockIdx.z;
    const float* A = (z == 0) ? q : (z == 1) ? k : v;
    const float* W = (z == 2) ? Wv : Wq;
    const float* bias = (z == 2) ? bv : bq;
    __half* Ch = (z == 0) ? Qh : (z == 1) ? Kh : Vh;
    __half* Cl = (z == 0) ? Ql : (z == 1) ? Kl : Vl;
    float scale = (z == 0) ? 0.17677669529663688f : 1.0f;
    gemm_tc_body(A, W, bias, nullptr, Ch, Cl, 1, scale);
}

__global__ __launch_bounds__(GT) void gemm_bias_kernel(
    const float* __restrict__ A, const float* __restrict__ W,
    const float* __restrict__ bias, float* __restrict__ C)
{
    gemm_tc_body(A, W, bias, C, nullptr, nullptr, 0, 1.0f);
}

// ---------------------------------------------------------------------------
// Fused attention: per block = one (b,h) and 32 query rows, 1024 threads.
// smem: sS[32][1028] fp32 | union { QK: Qh/Ql [32][40]h, Kh/Kl [256][40]h ;
//        PV: Vh/Vl [128][40]h, Ph/Pl [32][136]h, Part [32][256]f }
// ---------------------------------------------------------------------------
#define U_OFF     131584
#define SQH_OFF   (U_OFF)
#define SQL_OFF   (U_OFF + 2560)
#define SKH_OFF   (U_OFF + 5120)
#define SKL_OFF   (U_OFF + 25600)
#define SVH_OFF   (U_OFF)
#define SVL_OFF   (U_OFF + 10240)
#define SPH_OFF   (U_OFF + 20480)
#define SPL_OFF   (U_OFF + 29184)
#define SPART_OFF (U_OFF + 37888)
#define SMEM_BYTES (U_OFF + 70656)   // 202240

__global__ __launch_bounds__(THREADS, 1) void attn_kernel(
    const float* __restrict__ gammas, float* __restrict__ scores_out)
{
    extern __shared__ char sm[];
    float*  sS  = (float*)sm;
    __half* sQh = (__half*)(sm + SQH_OFF);
    __half* sQl = (__half*)(sm + SQL_OFF);
    __half* sKh = (__half*)(sm + SKH_OFF);
    __half* sKl = (__half*)(sm + SKL_OFF);
    __half* sVh = (__half*)(sm + SVH_OFF);
    __half* sVl = (__half*)(sm + SVL_OFF);
    __half* sPh = (__half*)(sm + SPH_OFF);
    __half* sPl = (__half*)(sm + SPL_OFF);
    float*  sPart = (float*)(sm + SPART_OFF);

    int tid = threadIdx.x;
    int lane = tid & 31, warp = tid >> 5;      // 32 warps
    int bh = blockIdx.y;
    int q0 = blockIdx.x * ROWS;
    int h = bh & (H_ - 1);
    int b = bh >> 3;
    size_t hbase = (size_t)bh * S_ * DH_;

    // ---- stage Q hi/lo (32 rows, pre-scaled in proj3) ----
    if (tid < 256) {
        int buf = tid >> 7, t = tid & 127;
        int r = t >> 2, s = t & 3;
        const __half* src = (buf ? g_Ql : g_Qh) + hbase + (size_t)(q0 + r) * DH_ + s * 8;
        __half* dst = (buf ? sQl : sQh) + r * 40 + s * 8;
        *(int4*)dst = *(const int4*)src;
    }
    __syncthreads();

    // QK mapping: rowTile = warp>>4 (0..1), colTile = warp&15 (0..15)
    int rowTile = warp >> 4;
    int colTile = warp & 15;
    wmma::fragment<wmma::matrix_a, 16, 16, 16, __half, wmma::row_major> qh0, qh1, ql0, ql1;
    wmma::load_matrix_sync(qh0, &sQh[rowTile * 16 * 40],      40);
    wmma::load_matrix_sync(qh1, &sQh[rowTile * 16 * 40 + 16], 40);
    wmma::load_matrix_sync(ql0, &sQl[rowTile * 16 * 40],      40);
    wmma::load_matrix_sync(ql1, &sQl[rowTile * 16 * 40 + 16], 40);

    int nchQK = (q0 + ROWS + 255) >> 8;
    for (int ch = 0; ch < nchQK; ch++) {
        int jb = ch << 8;
        __syncthreads();
        // stage K chunk (256 rows) hi/lo: 4096 int4 over 1024 threads
        #pragma unroll
        for (int it = 0; it < 4; it++) {
            int f = tid + it * THREADS;
            int buf = f >> 11, rem = f & 2047;
            int j = rem >> 2, s = rem & 3;
            const __half* src = (buf ? g_Kl : g_Kh) + hbase + (size_t)(jb + j) * DH_ + s * 8;
            __half* dst = (buf ? sKl : sKh) + j * 40 + s * 8;
            *(int4*)dst = *(const int4*)src;
        }
        __syncthreads();
        int jn = jb + colTile * 16;
        if (jn <= q0 + rowTile * 16) {        // tile touches unmasked region
            wmma::fragment<wmma::matrix_b, 16, 16, 16, __half, wmma::col_major> kh0, kh1, kl0, kl1;
            wmma::load_matrix_sync(kh0, &sKh[(colTile*16) * 40],      40);
            wmma::load_matrix_sync(kh1, &sKh[(colTile*16) * 40 + 16], 40);
            wmma::load_matrix_sync(kl0, &sKl[(colTile*16) * 40],      40);
            wmma::load_matrix_sync(kl1, &sKl[(colTile*16) * 40 + 16], 40);
            wmma::fragment<wmma::accumulator, 16, 16, 16, float> sacc;
            wmma::fill_fragment(sacc, 0.0f);
            wmma::mma_sync(sacc, qh0, kh0, sacc);
            wmma::mma_sync(sacc, qh1, kh1, sacc);
            wmma::mma_sync(sacc, qh0, kl0, sacc);
            wmma::mma_sync(sacc, qh1, kl1, sacc);
            wmma::mma_sync(sacc, ql0, kh0, sacc);
            wmma::mma_sync(sacc, ql1, kh1, sacc);
            wmma::store_matrix_sync(&sS[(size_t)(rowTile*16) * SS_STRIDE + jn],
                                    sacc, SS_STRIDE, wmma::mem_row_major);
        }
    }
    __syncthreads();

    // ---- row phase (1 row/warp, 32 warps): Z1, scan+decay, normalize ----
    {
        float gam = -fabsf(gammas[h]);
        int qg = q0 + warp;
        int L = qg + 1;
        float* row = sS + (size_t)warp * SS_STRIDE;

        float Z1 = 0.f;
        for (int j = lane * 4; j < L; j += 128) {
            float4 sv = *(const float4*)&row[j];
            if (j + 0 < L) Z1 += __expf(sv.x);
            if (j + 1 < L) Z1 += __expf(sv.y);
            if (j + 2 < L) Z1 += __expf(sv.z);
            if (j + 3 < L) Z1 += __expf(sv.w);
        }
        #pragma unroll
        for (int o = 16; o; o >>= 1) Z1 += __shfl_xor_sync(0xffffffffu, Z1, o);
        float invZ1 = __frcp_rn(Z1);

        float running = 0.f, Z2 = 0.f;
        int nb = (L + 127) >> 7;
        for (int bi = 0; bi < nb; bi++) {
            int j = bi * 128 + lane * 4;
            float4 sv = *(const float4*)&row[j];
            float e0 = (j + 0 < L) ? __expf(sv.x) : 0.f;
            float e1 = (j + 1 < L) ? __expf(sv.y) : 0.f;
            float e2 = (j + 2 < L) ? __expf(sv.z) : 0.f;
            float e3 = (j + 3 < L) ? __expf(sv.w) : 0.f;
            float p1 = e0 + e1, p2 = p1 + e2, p3 = p2 + e3;
            float c = p3;
            #pragma unroll
            for (int o = 1; o < 32; o <<= 1) {
                float t = __shfl_up_sync(0xffffffffu, c, o);
                if (lane >= o) c += t;
            }
            float excl = running + c - p3;
            running += __shfl_sync(0xffffffffu, c, 31);
            float4 out = {0.f, 0.f, 0.f, 0.f};
            if (j + 0 < L) {
                float rem = 1.f - (excl + e0) * invZ1;
                float dist = sqrtf(fmaxf(rem * (float)(qg - j), 0.f));
                float eff = fmaxf(__expf(gam * dist), 1e-5f);
                out.x = __expf(sv.x * eff); Z2 += out.x;
            }
            if (j + 1 < L) {
                float rem = 1.f - (excl + p1) * invZ1;
                float dist = sqrtf(fmaxf(rem * (float)(qg - j - 1), 0.f));
                float eff = fmaxf(__expf(gam * dist), 1e-5f);
                out.y = __expf(sv.y * eff); Z2 += out.y;
            }
            if (j + 2 < L) {
                float rem = 1.f - (excl + p2) * invZ1;
                float dist = sqrtf(fmaxf(rem * (float)(qg - j - 2), 0.f));
                float eff = fmaxf(__expf(gam * dist), 1e-5f);
                out.z = __expf(sv.z * eff); Z2 += out.z;
            }
            if (j + 3 < L) {
                float rem = 1.f - (excl + p3) * invZ1;
                float dist = sqrtf(fmaxf(rem * (float)(qg - j - 3), 0.f));
                float eff = fmaxf(__expf(gam * dist), 1e-5f);
                out.w = __expf(sv.w * eff); Z2 += out.w;
            }
            *(float4*)&row[j] = out;
        }
        #pragma unroll
        for (int o = 16; o; o >>= 1) Z2 += __shfl_xor_sync(0xffffffffu, Z2, o);
        float invZ2 = __frcp_rn(Z2);

        float* grow = scores_out + ((size_t)bh * S_ + qg) * S_;
        for (int j = lane * 4; j < S_; j += 128) {
            float4 pv = *(const float4*)&row[j];
            float4 p;
            p.x = (j + 0 < L) ? pv.x * invZ2 : 0.f;
            p.y = (j + 1 < L) ? pv.y * invZ2 : 0.f;
            p.z = (j + 2 < L) ? pv.z * invZ2 : 0.f;
            p.w = (j + 3 < L) ? pv.w * invZ2 : 0.f;
            *(float4*)&row[j] = p;
            __stcs((float4*)&grow[j], p);
        }
    }

    // ---- PV via HMMA: warp = kslot(0..7) x ntile(0..1) x rowhalf(0..1) ----
    int kslot = warp >> 2;
    int ntile = (warp >> 1) & 1;
    int rowhalf = warp & 1;
    wmma::fragment<wmma::accumulator, 16, 16, 16, float> accPV;
    wmma::fill_fragment(accPV, 0.0f);
    int nchPV = (q0 + ROWS + 127) >> 7;
    for (int ch = 0; ch < nchPV; ch++) {
        int jb = ch << 7;
        __syncthreads();
        {   // stage V chunk hi/lo: 1024 int4, one per thread
            int f = tid;
            int buf = f >> 9, rem = f & 511;
            int j = rem >> 2, s = rem & 3;
            const __half* src = (buf ? g_Vl : g_Vh) + hbase + (size_t)(jb + j) * DH_ + s * 8;
            __half* dst = (buf ? sVl : sVh) + j * 40 + s * 8;
            *(int4*)dst = *(const int4*)src;
        }
        // convert P chunk (32 rows x 128 cols) to fp16 hi/lo: 4 per thread
        #pragma unroll
        for (int it = 0; it < 4; it++) {
            int idx = tid + it * THREADS;
            int r = idx >> 7, c = idx & 127;
            float p = sS[(size_t)r * SS_STRIDE + jb + c];
            __half ph = __float2half_rn(p);
            sPh[r * 136 + c] = ph;
            sPl[r * 136 + c] = __float2half_rn(p - __half2float(ph));
        }
        __syncthreads();
        wmma::fragment<wmma::matrix_a, 16, 16, 16, __half, wmma::row_major> aph, apl;
        wmma::fragment<wmma::matrix_b, 16, 16, 16, __half, wmma::row_major> bvh, bvl;
        wmma::load_matrix_sync(aph, &sPh[(rowhalf*16) * 136 + kslot * 16], 136);
        wmma::load_matrix_sync(apl, &sPl[(rowhalf*16) * 136 + kslot * 16], 136);
        wmma::load_matrix_sync(bvh, &sVh[(kslot * 16) * 40 + ntile * 16], 40);
        wmma::load_matrix_sync(bvl, &sVl[(kslot * 16) * 40 + ntile * 16], 40);
        wmma::mma_sync(accPV, aph, bvh, accPV);
        wmma::mma_sync(accPV, aph, bvl, accPV);
        wmma::mma_sync(accPV, apl, bvh, accPV);
    }
    wmma::store_matrix_sync(&sPart[warp * 256], accPV, 16, wmma::mem_row_major);
    __syncthreads();

    // reduce 8 kslot partials per (ntile, rowhalf); warps 0..3 handle one each
    if (warp < 4) {
        int rntile = (warp >> 1) & 1;
        int rrowhalf = warp & 1;
        for (int e = lane; e < 256; e += 32) {
            float s = 0.f;
            #pragma unroll
            for (int k = 0; k < 8; k++)
                s += sPart[((k << 2) | warp) * 256 + e];
            int r = e >> 4, c = e & 15;
            g_ctx[((size_t)(b * S_ + q0 + rrowhalf * 16 + r)) * D_
                  + h * DH_ + rntile * 16 + c] = s;
        }
    }
}

// ---------------------------------------------------------------------------
extern "C" void kernel_launch(void* const* d_in, const int* in_sizes, int n_in,
                              void* d_out, int out_size) {
    const float* q      = (const float*)d_in[0];
    const float* k      = (const float*)d_in[1];
    const float* v      = (const float*)d_in[2];
    const float* Wq     = (const float*)d_in[4];
    const float* bq     = (const float*)d_in[5];
    const float* Wv     = (const float*)d_in[6];
    const float* bv     = (const float*)d_in[7];
    const float* Wo     = (const float*)d_in[8];
    const float* bo     = (const float*)d_in[9];
    const float* gammas = (const float*)d_in[10];

    float* out    = (float*)d_out;                       // [B,S,D]
    float* scores = out + (size_t)B_ * S_ * D_;          // [B,H,S,S]

    __half *Qh, *Ql, *Kh, *Kl, *Vh, *Vl;
    float* ctx;
    cudaGetSymbolAddress((void**)&Qh, g_Qh);
    cudaGetSymbolAddress((void**)&Ql, g_Ql);
    cudaGetSymbolAddress((void**)&Kh, g_Kh);
    cudaGetSymbolAddress((void**)&Kl, g_Kl);
    cudaGetSymbolAddress((void**)&Vh, g_Vh);
    cudaGetSymbolAddress((void**)&Vl, g_Vl);
    cudaGetSymbolAddress((void**)&ctx, g_ctx);

    cudaFuncSetAttribute(proj3_kernel, cudaFuncAttributeMaxDynamicSharedMemorySize, GS_TOTAL);
    cudaFuncSetAttribute(gemm_bias_kernel, cudaFuncAttributeMaxDynamicSharedMemorySize, GS_TOTAL);

    proj3_kernel<<<dim3(2, 64, 3), GT, GS_TOTAL>>>(q, k, v, Wq, bq, Wv, bv,
                                                   Qh, Ql, Kh, Kl, Vh, Vl);

    cudaFuncSetAttribute(attn_kernel, cudaFuncAttributeMaxDynamicSharedMemorySize, SMEM_BYTES);
    attn_kernel<<<dim3(S_ / ROWS, BH_), THREADS, SMEM_BYTES>>>(gammas, scores);

    gemm_bias_kernel<<<dim3(2, 64), GT, GS_TOTAL>>>(ctx, Wo, bo, out);
}

// round 16
// speedup vs baseline: 1.0449x; 1.0449x over previous
#include <cuda_runtime.h>
#include <cuda_bf16.h>
#include <cuda_fp16.h>
#include <mma.h>
#include <math.h>
#include <cstdint>

using namespace nvcuda;

#define B_ 8
#define S_ 1024
#define D_ 256
#define H_ 8
#define DH_ 32
#define BH_ (B_*H_)
#define ROWS 16
#define SS_STRIDE 1028
#define THREADS 512
#define GT 256
#define KCH 32
#define GLDA 40
#define LDC 132
#define GBUF_BYTES (4 * 128 * GLDA * 2)    // 40960 per buffer
#define GS_TOTAL (2 * GBUF_BYTES)          // 81920 (> C tile 67584, aliased)

// Scratch (device globals: no allocation allowed)
__device__ __half g_Qh[BH_*S_*DH_], g_Ql[BH_*S_*DH_];
__device__ __half g_Kh[BH_*S_*DH_], g_Kl[BH_*S_*DH_];
__device__ __half g_Vh[BH_*S_*DH_], g_Vl[BH_*S_*DH_];
__device__ float  g_ctx[B_*S_*D_];

__device__ __forceinline__ void cvt_store_bf(
    __nv_bfloat16* hi, __nv_bfloat16* lo, int off, float4 x)
{
    __nv_bfloat16 hx = __float2bfloat16_rn(x.x);
    __nv_bfloat16 hy = __float2bfloat16_rn(x.y);
    __nv_bfloat16 hz = __float2bfloat16_rn(x.z);
    __nv_bfloat16 hw = __float2bfloat16_rn(x.w);
    *(__nv_bfloat162*)&hi[off]     = __nv_bfloat162(hx, hy);
    *(__nv_bfloat162*)&hi[off + 2] = __nv_bfloat162(hz, hw);
    *(__nv_bfloat162*)&lo[off] = __nv_bfloat162(
        __float2bfloat16_rn(x.x - __bfloat162float(hx)),
        __float2bfloat16_rn(x.y - __bfloat162float(hy)));
    *(__nv_bfloat162*)&lo[off + 2] = __nv_bfloat162(
        __float2bfloat16_rn(x.z - __bfloat162float(hz)),
        __float2bfloat16_rn(x.w - __bfloat162float(hw)));
}

// ---------------------------------------------------------------------------
// Tensor-core GEMM (wmma bf16 split 3-term, double-buffered): C = A@W^T + bias
// ---------------------------------------------------------------------------
__device__ __forceinline__ void gemm_tc_body(
    const float* __restrict__ A, const float* __restrict__ W,
    const float* __restrict__ bias, float* __restrict__ Cf,
    __half* __restrict__ Ch, __half* __restrict__ Cl, int mode, float outScale)
{
    extern __shared__ char gsm[];
    float* sC = (float*)gsm;
    int tid = threadIdx.x;
    int warp = tid >> 5;
    int m0 = blockIdx.y * 128, n0 = blockIdx.x * 128;
    int mw = (warp >> 2) * 64;
    int nw = (warp & 3) * 32;

    wmma::fragment<wmma::accumulator, 16, 16, 16, float> acc[4][2];
    #pragma unroll
    for (int i = 0; i < 4; i++)
        #pragma unroll
        for (int j = 0; j < 2; j++)
            wmma::fill_fragment(acc[i][j], 0.0f);

    float4 pa[4], pb[4];
    #pragma unroll
    for (int it = 0; it < 4; it++) {
        int idx = tid + it * GT;
        int r = idx >> 3, c4 = (idx & 7) << 2;
        pa[it] = *(const float4*)&A[(size_t)(m0 + r) * D_ + c4];
        pb[it] = *(const float4*)&W[(size_t)(n0 + r) * D_ + c4];
    }

    for (int kc = 0; kc < D_; kc += KCH) {
        char* bufb = gsm + (((kc >> 5) & 1) ? GBUF_BYTES : 0);
        __nv_bfloat16* bAhi = (__nv_bfloat16*)bufb;
        __nv_bfloat16* bAlo = bAhi + 128 * GLDA;
        __nv_bfloat16* bBhi = bAlo + 128 * GLDA;
        __nv_bfloat16* bBlo = bBhi + 128 * GLDA;

        #pragma unroll
        for (int it = 0; it < 4; it++) {
            int idx = tid + it * GT;
            int r = idx >> 3, c4 = (idx & 7) << 2;
            cvt_store_bf(bAhi, bAlo, r * GLDA + c4, pa[it]);
            cvt_store_bf(bBhi, bBlo, r * GLDA + c4, pb[it]);
        }
        __syncthreads();

        if (kc + KCH < D_) {
            #pragma unroll
            for (int it = 0; it < 4; it++) {
                int idx = tid + it * GT;
                int r = idx >> 3, c4 = (idx & 7) << 2;
                pa[it] = *(const float4*)&A[(size_t)(m0 + r) * D_ + kc + KCH + c4];
                pb[it] = *(const float4*)&W[(size_t)(n0 + r) * D_ + kc + KCH + c4];
            }
        }

        #pragma unroll
        for (int kk = 0; kk < KCH; kk += 16) {
            wmma::fragment<wmma::matrix_a, 16, 16, 16, __nv_bfloat16, wmma::row_major> ah[4], al[4];
            wmma::fragment<wmma::matrix_b, 16, 16, 16, __nv_bfloat16, wmma::col_major> bh[2], bl[2];
            #pragma unroll
            for (int i = 0; i < 4; i++) {
                wmma::load_matrix_sync(ah[i], &bAhi[(mw + i*16) * GLDA + kk], GLDA);
                wmma::load_matrix_sync(al[i], &bAlo[(mw + i*16) * GLDA + kk], GLDA);
            }
            #pragma unroll
            for (int j = 0; j < 2; j++) {
                wmma::load_matrix_sync(bh[j], &bBhi[(nw + j*16) * GLDA + kk], GLDA);
                wmma::load_matrix_sync(bl[j], &bBlo[(nw + j*16) * GLDA + kk], GLDA);
            }
            #pragma unroll
            for (int i = 0; i < 4; i++)
                #pragma unroll
                for (int j = 0; j < 2; j++) {
                    wmma::mma_sync(acc[i][j], ah[i], bh[j], acc[i][j]);
                    wmma::mma_sync(acc[i][j], ah[i], bl[j], acc[i][j]);
                    wmma::mma_sync(acc[i][j], al[i], bh[j], acc[i][j]);
                }
        }
        __syncthreads();
    }

    #pragma unroll
    for (int i = 0; i < 4; i++)
        #pragma unroll
        for (int j = 0; j < 2; j++)
            wmma::store_matrix_sync(&sC[(mw + i*16) * LDC + nw + j*16],
                                    acc[i][j], LDC, wmma::mem_row_major);
    __syncthreads();

    #pragma unroll
    for (int it = 0; it < 16; it++) {
        int idx = tid + it * GT;
        int r = idx >> 5, c4 = (idx & 31) << 2;
        float4 v = *(const float4*)&sC[r * LDC + c4];
        int n = n0 + c4;
        v.x += bias[n]; v.y += bias[n+1]; v.z += bias[n+2]; v.w += bias[n+3];
        int m = m0 + r, bbat = m >> 10, ss = m & 1023;
        if (mode == 1) {
            v.x *= outScale; v.y *= outScale; v.z *= outScale; v.w *= outScale;
            int h = n >> 5, dh = n & 31;
            size_t base = (((size_t)(bbat * H_ + h)) * S_ + ss) * DH_ + dh;
            __half hx = __float2half_rn(v.x), hy = __float2half_rn(v.y);
            __half hz = __float2half_rn(v.z), hw = __float2half_rn(v.w);
            *(__half2*)&Ch[base]     = __halves2half2(hx, hy);
            *(__half2*)&Ch[base + 2] = __halves2half2(hz, hw);
            *(__half2*)&Cl[base] = __halves2half2(
                __float2half_rn(v.x - __half2float(hx)),
                __float2half_rn(v.y - __half2float(hy)));
            *(__half2*)&Cl[base + 2] = __halves2half2(
                __float2half_rn(v.z - __half2float(hz)),
                __float2half_rn(v.w - __half2float(hw)));
        } else {
            *(float4*)&Cf[(size_t)m * D_ + n] = v;
        }
    }
}

__global__ __launch_bounds__(GT) void proj3_kernel(
    const float* __restrict__ q, const float* __restrict__ k, const float* __restrict__ v,
    const float* __restrict__ Wq, const float* __restrict__ bq,
    const float* __restrict__ Wv, const float* __restrict__ bv,
    __half* Qh, __half* Ql, __half* Kh, __half* Kl, __half* Vh, __half* Vl)
{
    int z = blockIdx.z;
    const float* A = (z == 0) ? q : (z == 1) ? k : v;
    const float* W = (z == 2) ? Wv : Wq;
    const float* bias = (z == 2) ? bv : bq;
    __half* Ch = (z == 0) ? Qh : (z == 1) ? Kh : Vh;
    __half* Cl = (z == 0) ? Ql : (z == 1) ? Kl : Vl;
    float scale = (z == 0) ? 0.17677669529663688f : 1.0f;
    gemm_tc_body(A, W, bias, nullptr, Ch, Cl, 1, scale);
}

__global__ __launch_bounds__(GT) void gemm_bias_kernel(
    const float* __restrict__ A, const float* __restrict__ W,
    const float* __restrict__ bias, float* __restrict__ C)
{
    gemm_tc_body(A, W, bias, C, nullptr, nullptr, 0, 1.0f);
}

// ---------------------------------------------------------------------------
// Fused attention: per block = one (b,h) and 16 query rows, 512 threads.
// (R13 structure; PV uses 2-term P@V — P hi-half only)
// smem unions: QK needs 43520 B (largest) -> SMEM_BYTES = U_OFF + 43520.
// ---------------------------------------------------------------------------
#define U_OFF   65792
#define SQH_OFF (U_OFF)
#define SQL_OFF (U_OFF + 1280)
#define SKH_OFF (U_OFF + 2560)
#define SKL_OFF (U_OFF + 23040)
#define SVH_OFF (U_OFF)
#define SVL_OFF (U_OFF + 10240)
#define SPH_OFF (U_OFF + 20480)
#define SPART_OFF (U_OFF + 24832)
#define SMEM_BYTES (U_OFF + 43520)   // max(QK union 43520, PV union 41216)

__global__ __launch_bounds__(THREADS, 2) void attn_kernel(
    const float* __restrict__ gammas, float* __restrict__ scores_out)
{
    extern __shared__ char sm[];
    float*  sS  = (float*)sm;
    __half* sQh = (__half*)(sm + SQH_OFF);
    __half* sQl = (__half*)(sm + SQL_OFF);
    __half* sKh = (__half*)(sm + SKH_OFF);
    __half* sKl = (__half*)(sm + SKL_OFF);
    __half* sVh = (__half*)(sm + SVH_OFF);
    __half* sVl = (__half*)(sm + SVL_OFF);
    __half* sPh = (__half*)(sm + SPH_OFF);
    float*  sPart = (float*)(sm + SPART_OFF);

    int tid = threadIdx.x;
    int lane = tid & 31, warp = tid >> 5;
    int bh = blockIdx.y;
    int q0 = blockIdx.x * ROWS;
    int h = bh & (H_ - 1);
    int b = bh >> 3;
    size_t hbase = (size_t)bh * S_ * DH_;

    // ---- stage Q hi/lo (pre-scaled in proj3) ----
    if (tid < 128) {
        int buf = tid >> 6, t = tid & 63;
        int r = t >> 2, s = t & 3;
        const __half* src = (buf ? g_Ql : g_Qh) + hbase + (size_t)(q0 + r) * DH_ + s * 8;
        __half* dst = (buf ? sQl : sQh) + r * 40 + s * 8;
        *(int4*)dst = *(const int4*)src;
    }
    __syncthreads();

    wmma::fragment<wmma::matrix_a, 16, 16, 16, __half, wmma::row_major> qh0, qh1, ql0, ql1;
    wmma::load_matrix_sync(qh0, sQh,      40);
    wmma::load_matrix_sync(qh1, sQh + 16, 40);
    wmma::load_matrix_sync(ql0, sQl,      40);
    wmma::load_matrix_sync(ql1, sQl + 16, 40);

    int nchQK = (q0 + 16 + 255) >> 8;
    for (int ch = 0; ch < nchQK; ch++) {
        int jb = ch << 8;
        __syncthreads();
        for (int f = tid; f < 2048; f += THREADS) {
            int buf = f >> 10, rem = f & 1023;
            int j = rem >> 2, s = rem & 3;
            const __half* src = (buf ? g_Kl : g_Kh) + hbase + (size_t)(jb + j) * DH_ + s * 8;
            __half* dst = (buf ? sKl : sKh) + j * 40 + s * 8;
            *(int4*)dst = *(const int4*)src;
        }
        __syncthreads();
        int jn = jb + warp * 16;
        if (jn <= q0) {
            wmma::fragment<wmma::matrix_b, 16, 16, 16, __half, wmma::col_major> kh0, kh1, kl0, kl1;
            wmma::load_matrix_sync(kh0, &sKh[(warp*16) * 40],      40);
            wmma::load_matrix_sync(kh1, &sKh[(warp*16) * 40 + 16], 40);
            wmma::load_matrix_sync(kl0, &sKl[(warp*16) * 40],      40);
            wmma::load_matrix_sync(kl1, &sKl[(warp*16) * 40 + 16], 40);
            wmma::fragment<wmma::accumulator, 16, 16, 16, float> sacc;
            wmma::fill_fragment(sacc, 0.0f);
            wmma::mma_sync(sacc, qh0, kh0, sacc);
            wmma::mma_sync(sacc, qh1, kh1, sacc);
            wmma::mma_sync(sacc, qh0, kl0, sacc);
            wmma::mma_sync(sacc, qh1, kl1, sacc);
            wmma::mma_sync(sacc, ql0, kh0, sacc);
            wmma::mma_sync(sacc, ql1, kh1, sacc);
            wmma::store_matrix_sync(&sS[jn], sacc, SS_STRIDE, wmma::mem_row_major);
        }
    }
    __syncthreads();

    // ---- row phase (1 row/warp): Z1, scan+decay, normalize+write ----
    {
        float gam = -fabsf(gammas[h]);
        int qg = q0 + warp;
        int L = qg + 1;
        float* row = sS + (size_t)warp * SS_STRIDE;

        float Z1 = 0.f;
        for (int j = lane * 4; j < L; j += 128) {
            float4 sv = *(const float4*)&row[j];
            if (j + 0 < L) Z1 += __expf(sv.x);
            if (j + 1 < L) Z1 += __expf(sv.y);
            if (j + 2 < L) Z1 += __expf(sv.z);
            if (j + 3 < L) Z1 += __expf(sv.w);
        }
        #pragma unroll
        for (int o = 16; o; o >>= 1) Z1 += __shfl_xor_sync(0xffffffffu, Z1, o);
        float invZ1 = __frcp_rn(Z1);

        float running = 0.f, Z2 = 0.f;
        int nb = (L + 127) >> 7;
        for (int bi = 0; bi < nb; bi++) {
            int j = bi * 128 + lane * 4;
            float4 sv = *(const float4*)&row[j];
            float e0 = (j + 0 < L) ? __expf(sv.x) : 0.f;
            float e1 = (j + 1 < L) ? __expf(sv.y) : 0.f;
            float e2 = (j + 2 < L) ? __expf(sv.z) : 0.f;
            float e3 = (j + 3 < L) ? __expf(sv.w) : 0.f;
            float p1 = e0 + e1, p2 = p1 + e2, p3 = p2 + e3;
            float c = p3;
            #pragma unroll
            for (int o = 1; o < 32; o <<= 1) {
                float t = __shfl_up_sync(0xffffffffu, c, o);
                if (lane >= o) c += t;
            }
            float excl = running + c - p3;
            running += __shfl_sync(0xffffffffu, c, 31);
            float4 out = {0.f, 0.f, 0.f, 0.f};
            if (j + 0 < L) {
                float rem = 1.f - (excl + e0) * invZ1;
                float dist = sqrtf(fmaxf(rem * (float)(qg - j), 0.f));
                float eff = fmaxf(__expf(gam * dist), 1e-5f);
                out.x = __expf(sv.x * eff); Z2 += out.x;
            }
            if (j + 1 < L) {
                float rem = 1.f - (excl + p1) * invZ1;
                float dist = sqrtf(fmaxf(rem * (float)(qg - j - 1), 0.f));
                float eff = fmaxf(__expf(gam * dist), 1e-5f);
                out.y = __expf(sv.y * eff); Z2 += out.y;
            }
            if (j + 2 < L) {
                float rem = 1.f - (excl + p2) * invZ1;
                float dist = sqrtf(fmaxf(rem * (float)(qg - j - 2), 0.f));
                float eff = fmaxf(__expf(gam * dist), 1e-5f);
                out.z = __expf(sv.z * eff); Z2 += out.z;
            }
            if (j + 3 < L) {
                float rem = 1.f - (excl + p3) * invZ1;
                float dist = sqrtf(fmaxf(rem * (float)(qg - j - 3), 0.f));
                float eff = fmaxf(__expf(gam * dist), 1e-5f);
                out.w = __expf(sv.w * eff); Z2 += out.w;
            }
            *(float4*)&row[j] = out;
        }
        #pragma unroll
        for (int o = 16; o; o >>= 1) Z2 += __shfl_xor_sync(0xffffffffu, Z2, o);
        float invZ2 = __frcp_rn(Z2);

        float* grow = scores_out + ((size_t)bh * S_ + qg) * S_;
        for (int j = lane * 4; j < S_; j += 128) {
            float4 pv = *(const float4*)&row[j];
            float4 p;
            p.x = (j + 0 < L) ? pv.x * invZ2 : 0.f;
            p.y = (j + 1 < L) ? pv.y * invZ2 : 0.f;
            p.z = (j + 2 < L) ? pv.z * invZ2 : 0.f;
            p.w = (j + 3 < L) ? pv.w * invZ2 : 0.f;
            *(float4*)&row[j] = p;
            __stcs((float4*)&grow[j], p);
        }
    }

    // ---- PV via HMMA (2-term: Ph*Vh + Ph*Vl) ----
    int kslot = warp & 7, ntile = warp >> 3;
    wmma::fragment<wmma::accumulator, 16, 16, 16, float> accPV;
    wmma::fill_fragment(accPV, 0.0f);
    int nchPV = (q0 + 16 + 127) >> 7;
    for (int ch = 0; ch < nchPV; ch++) {
        int jb = ch << 7;
        __syncthreads();
        for (int f = tid; f < 1024; f += THREADS) {
            int buf = f >> 9, rem = f & 511;
            int j = rem >> 2, s = rem & 3;
            const __half* src = (buf ? g_Vl : g_Vh) + hbase + (size_t)(jb + j) * DH_ + s * 8;
            __half* dst = (buf ? sVl : sVh) + j * 40 + s * 8;
            *(int4*)dst = *(const int4*)src;
        }
        for (int idx = tid; idx < 2048; idx += THREADS) {
            int r = idx >> 7, c = idx & 127;
            float p = sS[(size_t)r * SS_STRIDE + jb + c];
            sPh[r * 136 + c] = __float2half_rn(p);
        }
        __syncthreads();
        wmma::fragment<wmma::matrix_a, 16, 16, 16, __half, wmma::row_major> aph;
        wmma::fragment<wmma::matrix_b, 16, 16, 16, __half, wmma::row_major> bvh, bvl;
        wmma::load_matrix_sync(aph, &sPh[kslot * 16], 136);
        wmma::load_matrix_sync(bvh, &sVh[(kslot * 16) * 40 + ntile * 16], 40);
        wmma::load_matrix_sync(bvl, &sVl[(kslot * 16) * 40 + ntile * 16], 40);
        wmma::mma_sync(accPV, aph, bvh, accPV);
        wmma::mma_sync(accPV, aph, bvl, accPV);
    }
    wmma::store_matrix_sync(&sPart[warp * 256], accPV, 16, wmma::mem_row_major);
    __syncthreads();

    if (warp < 2) {
        for (int e = lane; e < 256; e += 32) {
            float s = 0.f;
            #pragma unroll
            for (int k = 0; k < 8; k++)
                s += sPart[(warp * 8 + k) * 256 + e];
            int r = e >> 4, c = e & 15;
            g_ctx[((size_t)(b * S_ + q0 + r)) * D_ + h * DH_ + warp * 16 + c] = s;
        }
    }
}

// ---------------------------------------------------------------------------
extern "C" void kernel_launch(void* const* d_in, const int* in_sizes, int n_in,
                              void* d_out, int out_size) {
    const float* q      = (const float*)d_in[0];
    const float* k      = (const float*)d_in[1];
    const float* v      = (const float*)d_in[2];
    const float* Wq     = (const float*)d_in[4];
    const float* bq     = (const float*)d_in[5];
    const float* Wv     = (const float*)d_in[6];
    const float* bv     = (const float*)d_in[7];
    const float* Wo     = (const float*)d_in[8];
    const float* bo     = (const float*)d_in[9];
    const float* gammas = (const float*)d_in[10];

    float* out    = (float*)d_out;                       // [B,S,D]
    float* scores = out + (size_t)B_ * S_ * D_;          // [B,H,S,S]

    __half *Qh, *Ql, *Kh, *Kl, *Vh, *Vl;
    float* ctx;
    cudaGetSymbolAddress((void**)&Qh, g_Qh);
    cudaGetSymbolAddress((void**)&Ql, g_Ql);
    cudaGetSymbolAddress((void**)&Kh, g_Kh);
    cudaGetSymbolAddress((void**)&Kl, g_Kl);
    cudaGetSymbolAddress((void**)&Vh, g_Vh);
    cudaGetSymbolAddress((void**)&Vl, g_Vl);
    cudaGetSymbolAddress((void**)&ctx, g_ctx);

    cudaFuncSetAttribute(proj3_kernel, cudaFuncAttributeMaxDynamicSharedMemorySize, GS_TOTAL);
    cudaFuncSetAttribute(gemm_bias_kernel, cudaFuncAttributeMaxDynamicSharedMemorySize, GS_TOTAL);

    proj3_kernel<<<dim3(2, 64, 3), GT, GS_TOTAL>>>(q, k, v, Wq, bq, Wv, bv,
                                                   Qh, Ql, Kh, Kl, Vh, Vl);

    cudaFuncSetAttribute(attn_kernel, cudaFuncAttributeMaxDynamicSharedMemorySize, SMEM_BYTES);
    attn_kernel<<<dim3(S_ / ROWS, BH_), THREADS, SMEM_BYTES>>>(gammas, scores);

    gemm_bias_kernel<<<dim3(2, 64), GT, GS_TOTAL>>>(ctx, Wo, bo, out);
}

// round 17
// speedup vs baseline: 1.1291x; 1.0806x over previous
#include <cuda_runtime.h>
#include <cuda_bf16.h>
#include <cuda_fp16.h>
#include <mma.h>
#include <math.h>
#include <cstdint>

using namespace nvcuda;

#define B_ 8
#define S_ 1024
#define D_ 256
#define H_ 8
#define DH_ 32
#define BH_ (B_*H_)
#define ROWS 16
#define SS_STRIDE 1028
#define THREADS 512
#define GT 256
#define KCH 32
#define GLDA 40
#define LDC 132
#define GBUF_BYTES (4 * 128 * GLDA * 2)    // 40960 per buffer
#define GS_TOTAL (2 * GBUF_BYTES)          // 81920 (> C tile 67584, aliased)

// Scratch (device globals: no allocation allowed)
__device__ __half g_Qh[BH_*S_*DH_], g_Ql[BH_*S_*DH_];
__device__ __half g_Kh[BH_*S_*DH_], g_Kl[BH_*S_*DH_];
__device__ __half g_Vh[BH_*S_*DH_], g_Vl[BH_*S_*DH_];
__device__ float  g_ctx[B_*S_*D_];

__device__ __forceinline__ void cvt_store_bf(
    __nv_bfloat16* hi, __nv_bfloat16* lo, int off, float4 x)
{
    __nv_bfloat16 hx = __float2bfloat16_rn(x.x);
    __nv_bfloat16 hy = __float2bfloat16_rn(x.y);
    __nv_bfloat16 hz = __float2bfloat16_rn(x.z);
    __nv_bfloat16 hw = __float2bfloat16_rn(x.w);
    *(__nv_bfloat162*)&hi[off]     = __nv_bfloat162(hx, hy);
    *(__nv_bfloat162*)&hi[off + 2] = __nv_bfloat162(hz, hw);
    *(__nv_bfloat162*)&lo[off] = __nv_bfloat162(
        __float2bfloat16_rn(x.x - __bfloat162float(hx)),
        __float2bfloat16_rn(x.y - __bfloat162float(hy)));
    *(__nv_bfloat162*)&lo[off + 2] = __nv_bfloat162(
        __float2bfloat16_rn(x.z - __bfloat162float(hz)),
        __float2bfloat16_rn(x.w - __bfloat162float(hw)));
}

// ---------------------------------------------------------------------------
// Tensor-core GEMM (wmma bf16 split 3-term, double-buffered): C = A@W^T + bias
// ---------------------------------------------------------------------------
__device__ __forceinline__ void gemm_tc_body(
    const float* __restrict__ A, const float* __restrict__ W,
    const float* __restrict__ bias, float* __restrict__ Cf,
    __half* __restrict__ Ch, __half* __restrict__ Cl, int mode, float outScale)
{
    extern __shared__ char gsm[];
    float* sC = (float*)gsm;
    int tid = threadIdx.x;
    int warp = tid >> 5;
    int m0 = blockIdx.y * 128, n0 = blockIdx.x * 128;
    int mw = (warp >> 2) * 64;
    int nw = (warp & 3) * 32;

    wmma::fragment<wmma::accumulator, 16, 16, 16, float> acc[4][2];
    #pragma unroll
    for (int i = 0; i < 4; i++)
        #pragma unroll
        for (int j = 0; j < 2; j++)
            wmma::fill_fragment(acc[i][j], 0.0f);

    float4 pa[4], pb[4];
    #pragma unroll
    for (int it = 0; it < 4; it++) {
        int idx = tid + it * GT;
        int r = idx >> 3, c4 = (idx & 7) << 2;
        pa[it] = *(const float4*)&A[(size_t)(m0 + r) * D_ + c4];
        pb[it] = *(const float4*)&W[(size_t)(n0 + r) * D_ + c4];
    }

    for (int kc = 0; kc < D_; kc += KCH) {
        char* bufb = gsm + (((kc >> 5) & 1) ? GBUF_BYTES : 0);
        __nv_bfloat16* bAhi = (__nv_bfloat16*)bufb;
        __nv_bfloat16* bAlo = bAhi + 128 * GLDA;
        __nv_bfloat16* bBhi = bAlo + 128 * GLDA;
        __nv_bfloat16* bBlo = bBhi + 128 * GLDA;

        #pragma unroll
        for (int it = 0; it < 4; it++) {
            int idx = tid + it * GT;
            int r = idx >> 3, c4 = (idx & 7) << 2;
            cvt_store_bf(bAhi, bAlo, r * GLDA + c4, pa[it]);
            cvt_store_bf(bBhi, bBlo, r * GLDA + c4, pb[it]);
        }
        __syncthreads();

        if (kc + KCH < D_) {
            #pragma unroll
            for (int it = 0; it < 4; it++) {
                int idx = tid + it * GT;
                int r = idx >> 3, c4 = (idx & 7) << 2;
                pa[it] = *(const float4*)&A[(size_t)(m0 + r) * D_ + kc + KCH + c4];
                pb[it] = *(const float4*)&W[(size_t)(n0 + r) * D_ + kc + KCH + c4];
            }
        }

        #pragma unroll
        for (int kk = 0; kk < KCH; kk += 16) {
            wmma::fragment<wmma::matrix_a, 16, 16, 16, __nv_bfloat16, wmma::row_major> ah[4], al[4];
            wmma::fragment<wmma::matrix_b, 16, 16, 16, __nv_bfloat16, wmma::col_major> bh[2], bl[2];
            #pragma unroll
            for (int i = 0; i < 4; i++) {
                wmma::load_matrix_sync(ah[i], &bAhi[(mw + i*16) * GLDA + kk], GLDA);
                wmma::load_matrix_sync(al[i], &bAlo[(mw + i*16) * GLDA + kk], GLDA);
            }
            #pragma unroll
            for (int j = 0; j < 2; j++) {
                wmma::load_matrix_sync(bh[j], &bBhi[(nw + j*16) * GLDA + kk], GLDA);
                wmma::load_matrix_sync(bl[j], &bBlo[(nw + j*16) * GLDA + kk], GLDA);
            }
            #pragma unroll
            for (int i = 0; i < 4; i++)
                #pragma unroll
                for (int j = 0; j < 2; j++) {
                    wmma::mma_sync(acc[i][j], ah[i], bh[j], acc[i][j]);
                    wmma::mma_sync(acc[i][j], ah[i], bl[j], acc[i][j]);
                    wmma::mma_sync(acc[i][j], al[i], bh[j], acc[i][j]);
                }
        }
        __syncthreads();
    }

    #pragma unroll
    for (int i = 0; i < 4; i++)
        #pragma unroll
        for (int j = 0; j < 2; j++)
            wmma::store_matrix_sync(&sC[(mw + i*16) * LDC + nw + j*16],
                                    acc[i][j], LDC, wmma::mem_row_major);
    __syncthreads();

    #pragma unroll
    for (int it = 0; it < 16; it++) {
        int idx = tid + it * GT;
        int r = idx >> 5, c4 = (idx & 31) << 2;
        float4 v = *(const float4*)&sC[r * LDC + c4];
        int n = n0 + c4;
        v.x += bias[n]; v.y += bias[n+1]; v.z += bias[n+2]; v.w += bias[n+3];
        int m = m0 + r, bbat = m >> 10, ss = m & 1023;
        if (mode == 1) {
            v.x *= outScale; v.y *= outScale; v.z *= outScale; v.w *= outScale;
            int h = n >> 5, dh = n & 31;
            size_t base = (((size_t)(bbat * H_ + h)) * S_ + ss) * DH_ + dh;
            __half hx = __float2half_rn(v.x), hy = __float2half_rn(v.y);
            __half hz = __float2half_rn(v.z), hw = __float2half_rn(v.w);
            *(__half2*)&Ch[base]     = __halves2half2(hx, hy);
            *(__half2*)&Ch[base + 2] = __halves2half2(hz, hw);
            *(__half2*)&Cl[base] = __halves2half2(
                __float2half_rn(v.x - __half2float(hx)),
                __float2half_rn(v.y - __half2float(hy)));
            *(__half2*)&Cl[base + 2] = __halves2half2(
                __float2half_rn(v.z - __half2float(hz)),
                __float2half_rn(v.w - __half2float(hw)));
        } else {
            *(float4*)&Cf[(size_t)m * D_ + n] = v;
        }
    }
}

__global__ __launch_bounds__(GT) void proj3_kernel(
    const float* __restrict__ q, const float* __restrict__ k, const float* __restrict__ v,
    const float* __restrict__ Wq, const float* __restrict__ bq,
    const float* __restrict__ Wv, const float* __restrict__ bv,
    __half* Qh, __half* Ql, __half* Kh, __half* Kl, __half* Vh, __half* Vl)
{
    int z = blockIdx.z;
    const float* A = (z == 0) ? q : (z == 1) ? k : v;
    const float* W = (z == 2) ? Wv : Wq;
    const float* bias = (z == 2) ? bv : bq;
    __half* Ch = (z == 0) ? Qh : (z == 1) ? Kh : Vh;
    __half* Cl = (z == 0) ? Ql : (z == 1) ? Kl : Vl;
    float scale = (z == 0) ? 0.17677669529663688f : 1.0f;
    gemm_tc_body(A, W, bias, nullptr, Ch, Cl, 1, scale);
}

__global__ __launch_bounds__(GT) void gemm_bias_kernel(
    const float* __restrict__ A, const float* __restrict__ W,
    const float* __restrict__ bias, float* __restrict__ C)
{
    gemm_tc_body(A, W, bias, C, nullptr, nullptr, 0, 1.0f);
}

// ---------------------------------------------------------------------------
// Fused attention: per block = one (b,h) and 16 query rows, 512 threads.
// QK: 2-term, K hi-only: s = (Qh+Ql)·Kh (4 MMAs). PV: 2-term Ph·(Vh+Vl).
// smem unions: QK = 23040 B, PV = 41216 B -> SMEM_BYTES = U_OFF + 41216.
// ---------------------------------------------------------------------------
#define U_OFF   65792
#define SQH_OFF (U_OFF)
#define SQL_OFF (U_OFF + 1280)
#define SKH_OFF (U_OFF + 2560)
#define SVH_OFF (U_OFF)
#define SVL_OFF (U_OFF + 10240)
#define SPH_OFF (U_OFF + 20480)
#define SPART_OFF (U_OFF + 24832)
#define SMEM_BYTES (U_OFF + 41216)   // max(QK 23040, PV 41216)

__global__ __launch_bounds__(THREADS, 2) void attn_kernel(
    const float* __restrict__ gammas, float* __restrict__ scores_out)
{
    extern __shared__ char sm[];
    float*  sS  = (float*)sm;
    __half* sQh = (__half*)(sm + SQH_OFF);
    __half* sQl = (__half*)(sm + SQL_OFF);
    __half* sKh = (__half*)(sm + SKH_OFF);
    __half* sVh = (__half*)(sm + SVH_OFF);
    __half* sVl = (__half*)(sm + SVL_OFF);
    __half* sPh = (__half*)(sm + SPH_OFF);
    float*  sPart = (float*)(sm + SPART_OFF);

    int tid = threadIdx.x;
    int lane = tid & 31, warp = tid >> 5;
    int bh = blockIdx.y;
    int q0 = blockIdx.x * ROWS;
    int h = bh & (H_ - 1);
    int b = bh >> 3;
    size_t hbase = (size_t)bh * S_ * DH_;

    // ---- stage Q hi/lo (pre-scaled in proj3) ----
    if (tid < 128) {
        int buf = tid >> 6, t = tid & 63;
        int r = t >> 2, s = t & 3;
        const __half* src = (buf ? g_Ql : g_Qh) + hbase + (size_t)(q0 + r) * DH_ + s * 8;
        __half* dst = (buf ? sQl : sQh) + r * 40 + s * 8;
        *(int4*)dst = *(const int4*)src;
    }
    __syncthreads();

    wmma::fragment<wmma::matrix_a, 16, 16, 16, __half, wmma::row_major> qh0, qh1, ql0, ql1;
    wmma::load_matrix_sync(qh0, sQh,      40);
    wmma::load_matrix_sync(qh1, sQh + 16, 40);
    wmma::load_matrix_sync(ql0, sQl,      40);
    wmma::load_matrix_sync(ql1, sQl + 16, 40);

    int nchQK = (q0 + 16 + 255) >> 8;
    for (int ch = 0; ch < nchQK; ch++) {
        int jb = ch << 8;
        __syncthreads();
        // stage K hi only: 1024 int4 (256 rows x 4 int4)
        for (int f = tid; f < 1024; f += THREADS) {
            int j = f >> 2, s = f & 3;
            const __half* src = g_Kh + hbase + (size_t)(jb + j) * DH_ + s * 8;
            *(int4*)(sKh + j * 40 + s * 8) = *(const int4*)src;
        }
        __syncthreads();
        int jn = jb + warp * 16;
        if (jn <= q0) {
            wmma::fragment<wmma::matrix_b, 16, 16, 16, __half, wmma::col_major> kh0, kh1;
            wmma::load_matrix_sync(kh0, &sKh[(warp*16) * 40],      40);
            wmma::load_matrix_sync(kh1, &sKh[(warp*16) * 40 + 16], 40);
            wmma::fragment<wmma::accumulator, 16, 16, 16, float> sacc;
            wmma::fill_fragment(sacc, 0.0f);
            wmma::mma_sync(sacc, qh0, kh0, sacc);
            wmma::mma_sync(sacc, qh1, kh1, sacc);
            wmma::mma_sync(sacc, ql0, kh0, sacc);
            wmma::mma_sync(sacc, ql1, kh1, sacc);
            wmma::store_matrix_sync(&sS[jn], sacc, SS_STRIDE, wmma::mem_row_major);
        }
    }
    __syncthreads();

    // ---- row phase (1 row/warp): Z1, scan+decay, normalize+write ----
    {
        float gam = -fabsf(gammas[h]);
        int qg = q0 + warp;
        int L = qg + 1;
        float* row = sS + (size_t)warp * SS_STRIDE;

        float Z1 = 0.f;
        for (int j = lane * 4; j < L; j += 128) {
            float4 sv = *(const float4*)&row[j];
            if (j + 0 < L) Z1 += __expf(sv.x);
            if (j + 1 < L) Z1 += __expf(sv.y);
            if (j + 2 < L) Z1 += __expf(sv.z);
            if (j + 3 < L) Z1 += __expf(sv.w);
        }
        #pragma unroll
        for (int o = 16; o; o >>= 1) Z1 += __shfl_xor_sync(0xffffffffu, Z1, o);
        float invZ1 = __frcp_rn(Z1);

        float running = 0.f, Z2 = 0.f;
        int nb = (L + 127) >> 7;
        for (int bi = 0; bi < nb; bi++) {
            int j = bi * 128 + lane * 4;
            float4 sv = *(const float4*)&row[j];
            float e0 = (j + 0 < L) ? __expf(sv.x) : 0.f;
            float e1 = (j + 1 < L) ? __expf(sv.y) : 0.f;
            float e2 = (j + 2 < L) ? __expf(sv.z) : 0.f;
            float e3 = (j + 3 < L) ? __expf(sv.w) : 0.f;
            float p1 = e0 + e1, p2 = p1 + e2, p3 = p2 + e3;
            float c = p3;
            #pragma unroll
            for (int o = 1; o < 32; o <<= 1) {
                float t = __shfl_up_sync(0xffffffffu, c, o);
                if (lane >= o) c += t;
            }
            float excl = running + c - p3;
            running += __shfl_sync(0xffffffffu, c, 31);
            float4 out = {0.f, 0.f, 0.f, 0.f};
            if (j + 0 < L) {
                float rem = 1.f - (excl + e0) * invZ1;
                float dist = sqrtf(fmaxf(rem * (float)(qg - j), 0.f));
                float eff = fmaxf(__expf(gam * dist), 1e-5f);
                out.x = __expf(sv.x * eff); Z2 += out.x;
            }
            if (j + 1 < L) {
                float rem = 1.f - (excl + p1) * invZ1;
                float dist = sqrtf(fmaxf(rem * (float)(qg - j - 1), 0.f));
                float eff = fmaxf(__expf(gam * dist), 1e-5f);
                out.y = __expf(sv.y * eff); Z2 += out.y;
            }
            if (j + 2 < L) {
                float rem = 1.f - (excl + p2) * invZ1;
                float dist = sqrtf(fmaxf(rem * (float)(qg - j - 2), 0.f));
                float eff = fmaxf(__expf(gam * dist), 1e-5f);
                out.z = __expf(sv.z * eff); Z2 += out.z;
            }
            if (j + 3 < L) {
                float rem = 1.f - (excl + p3) * invZ1;
                float dist = sqrtf(fmaxf(rem * (float)(qg - j - 3), 0.f));
                float eff = fmaxf(__expf(gam * dist), 1e-5f);
                out.w = __expf(sv.w * eff); Z2 += out.w;
            }
            *(float4*)&row[j] = out;
        }
        #pragma unroll
        for (int o = 16; o; o >>= 1) Z2 += __shfl_xor_sync(0xffffffffu, Z2, o);
        float invZ2 = __frcp_rn(Z2);

        float* grow = scores_out + ((size_t)bh * S_ + qg) * S_;
        for (int j = lane * 4; j < S_; j += 128) {
            float4 pv = *(const float4*)&row[j];
            float4 p;
            p.x = (j + 0 < L) ? pv.x * invZ2 : 0.f;
            p.y = (j + 1 < L) ? pv.y * invZ2 : 0.f;
            p.z = (j + 2 < L) ? pv.z * invZ2 : 0.f;
            p.w = (j + 3 < L) ? pv.w * invZ2 : 0.f;
            *(float4*)&row[j] = p;
            __stcs((float4*)&grow[j], p);
        }
    }

    // ---- PV via HMMA (2-term: Ph*Vh + Ph*Vl) ----
    int kslot = warp & 7, ntile = warp >> 3;
    wmma::fragment<wmma::accumulator, 16, 16, 16, float> accPV;
    wmma::fill_fragment(accPV, 0.0f);
    int nchPV = (q0 + 16 + 127) >> 7;
    for (int ch = 0; ch < nchPV; ch++) {
        int jb = ch << 7;
        __syncthreads();
        for (int f = tid; f < 1024; f += THREADS) {
            int buf = f >> 9, rem = f & 511;
            int j = rem >> 2, s = rem & 3;
            const __half* src = (buf ? g_Vl : g_Vh) + hbase + (size_t)(jb + j) * DH_ + s * 8;
            __half* dst = (buf ? sVl : sVh) + j * 40 + s * 8;
            *(int4*)dst = *(const int4*)src;
        }
        for (int idx = tid; idx < 2048; idx += THREADS) {
            int r = idx >> 7, c = idx & 127;
            float p = sS[(size_t)r * SS_STRIDE + jb + c];
            sPh[r * 136 + c] = __float2half_rn(p);
        }
        __syncthreads();
        wmma::fragment<wmma::matrix_a, 16, 16, 16, __half, wmma::row_major> aph;
        wmma::fragment<wmma::matrix_b, 16, 16, 16, __half, wmma::row_major> bvh, bvl;
        wmma::load_matrix_sync(aph, &sPh[kslot * 16], 136);
        wmma::load_matrix_sync(bvh, &sVh[(kslot * 16) * 40 + ntile * 16], 40);
        wmma::load_matrix_sync(bvl, &sVl[(kslot * 16) * 40 + ntile * 16], 40);
        wmma::mma_sync(accPV, aph, bvh, accPV);
        wmma::mma_sync(accPV, aph, bvl, accPV);
    }
    wmma::store_matrix_sync(&sPart[warp * 256], accPV, 16, wmma::mem_row_major);
    __syncthreads();

    if (warp < 2) {
        for (int e = lane; e < 256; e += 32) {
            float s = 0.f;
            #pragma unroll
            for (int k = 0; k < 8; k++)
                s += sPart[(warp * 8 + k) * 256 + e];
            int r = e >> 4, c = e & 15;
            g_ctx[((size_t)(b * S_ + q0 + r)) * D_ + h * DH_ + warp * 16 + c] = s;
        }
    }
}

// ---------------------------------------------------------------------------
extern "C" void kernel_launch(void* const* d_in, const int* in_sizes, int n_in,
                              void* d_out, int out_size) {
    const float* q      = (const float*)d_in[0];
    const float* k      = (const float*)d_in[1];
    const float* v      = (const float*)d_in[2];
    const float* Wq     = (const float*)d_in[4];
    const float* bq     = (const float*)d_in[5];
    const float* Wv     = (const float*)d_in[6];
    const float* bv     = (const float*)d_in[7];
    const float* Wo     = (const float*)d_in[8];
    const float* bo     = (const float*)d_in[9];
    const float* gammas = (const float*)d_in[10];

    float* out    = (float*)d_out;                       // [B,S,D]
    float* scores = out + (size_t)B_ * S_ * D_;          // [B,H,S,S]

    __half *Qh, *Ql, *Kh, *Kl, *Vh, *Vl;
    float* ctx;
    cudaGetSymbolAddress((void**)&Qh, g_Qh);
    cudaGetSymbolAddress((void**)&Ql, g_Ql);
    cudaGetSymbolAddress((void**)&Kh, g_Kh);
    cudaGetSymbolAddress((void**)&Kl, g_Kl);
    cudaGetSymbolAddress((void**)&Vh, g_Vh);
    cudaGetSymbolAddress((void**)&Vl, g_Vl);
    cudaGetSymbolAddress((void**)&ctx, g_ctx);

    cudaFuncSetAttribute(proj3_kernel, cudaFuncAttributeMaxDynamicSharedMemorySize, GS_TOTAL);
    cudaFuncSetAttribute(gemm_bias_kernel, cudaFuncAttributeMaxDynamicSharedMemorySize, GS_TOTAL);

    proj3_kernel<<<dim3(2, 64, 3), GT, GS_TOTAL>>>(q, k, v, Wq, bq, Wv, bv,
                                                   Qh, Ql, Kh, Kl, Vh, Vl);

    cudaFuncSetAttribute(attn_kernel, cudaFuncAttributeMaxDynamicSharedMemorySize, SMEM_BYTES);
    attn_kernel<<<dim3(S_ / ROWS, BH_), THREADS, SMEM_BYTES>>>(gammas, scores);

    gemm_bias_kernel<<<dim3(2, 64), GT, GS_TOTAL>>>(ctx, Wo, bo, out);
}